// round 1
// baseline (speedup 1.0000x reference)
#include <cuda_runtime.h>
#include <cstdint>
#include <math.h>

// Problem shape (fixed by the reference)
#define NB 32
#define NT 2048
#define ND 128
#define NC 64          // number of time chunks
#define CH 32          // timesteps per chunk (NT / NC)

// ---------------------------------------------------------------------------
// Scratch (no allocations allowed -> __device__ globals)
// Chunk summaries: forward = last observed (x,t) in chunk,
//                  backward = first observed (x,t) in chunk.
// ---------------------------------------------------------------------------
__device__ int g_is_bool;                       // 1 if mask is 1-byte, 0 if int32
__device__ float         g_fx[NB * NC * ND];
__device__ float         g_ft[NB * NC * ND];
__device__ unsigned char g_fv[NB * NC * ND];
__device__ float         g_bx[NB * NC * ND];
__device__ float         g_bt[NB * NC * ND];
__device__ unsigned char g_bv[NB * NC * ND];

__global__ void k_init_flag() { g_is_bool = 0; }

// Detect mask storage: int32 0/1 mask -> every 32-bit word is 0 or 1.
// Packed 1-byte bools -> words like 0x00010001 appear with overwhelming
// probability over 256K random words. Scans only the first 1MB (safe for
// both layouts: bool buffer is 8MB, int32 buffer is 32MB).
__global__ void k_detect(const unsigned int* __restrict__ w, int nwords) {
    int i = blockIdx.x * blockDim.x + threadIdx.x;
    if (i < nwords && w[i] > 1u) g_is_bool = 1;
}

__device__ __forceinline__ bool read_mask(const void* m, int idx, bool isb) {
    if (isb) return ((const unsigned char*)m)[idx] != 0;
    return ((const int*)m)[idx] != 0;
}

// ---------------------------------------------------------------------------
// Pass 1: per-chunk summaries. Block = (b, chunk c); thread = lane d.
// All global loads are fully coalesced (128 consecutive d per timestep).
// ---------------------------------------------------------------------------
__global__ void __launch_bounds__(ND) k_sum(const float* __restrict__ v,
                                            const float* __restrict__ t,
                                            const void*  __restrict__ mraw) {
    const bool isb = (g_is_bool != 0);
    const int blk = blockIdx.x;           // 0 .. NB*NC-1
    const int b = blk / NC;
    const int c = blk % NC;
    const int d = threadIdx.x;

    int base = (b * NT + c * CH) * ND + d;

    float lx = 0.f, lt = 0.f, fx = 0.f, ft = 0.f;
    bool  lv = false, fv = false;

#pragma unroll 8
    for (int tt = 0; tt < CH; ++tt) {
        int idx = base + tt * ND;
        bool m = read_mask(mraw, idx, isb);
        if (m) {
            float vv = v[idx];
            float tv = t[idx];
            lx = vv; lt = tv; lv = true;           // last observed in chunk
            if (!fv) { fx = vv; ft = tv; fv = true; }  // first observed
        }
    }

    int s = blk * ND + d;
    g_fx[s] = lx; g_ft[s] = lt; g_fv[s] = (unsigned char)lv;
    g_bx[s] = fx; g_bt[s] = ft; g_bv[s] = (unsigned char)fv;
}

// ---------------------------------------------------------------------------
// Pass 2: seed from summaries, backward sweep into smem, forward sweep
// computing the reference interpolation exactly.
// ---------------------------------------------------------------------------
__global__ void __launch_bounds__(ND) k_interp(const float* __restrict__ v,
                                               const float* __restrict__ t,
                                               const void*  __restrict__ mraw,
                                               float* __restrict__ out) {
    __shared__ float2 s_next[CH][ND];    // (x_next, t_next) per position, 32KB

    const bool isb = (g_is_bool != 0);
    const int blk = blockIdx.x;
    const int b = blk / NC;
    const int c = blk % NC;
    const int d = threadIdx.x;

    const int rowbase = b * NT * ND + d;
    const float t0   = t[rowbase];                    // times[b, 0,    d]
    const float tmax = t[rowbase + (NT - 1) * ND];    // times[b, T-1,  d] == max (cumsum)
    const int base = rowbase + (c * CH) * ND;

    // ---- backward seed: first observation in any later chunk ----
    float nx = 0.f, ntm = tmax; bool nv = false;
    for (int j = c + 1; j < NC; ++j) {
        int s = (b * NC + j) * ND + d;
        if (g_bv[s]) { nx = g_bx[s]; ntm = g_bt[s]; nv = true; break; }
    }

    // ---- backward sweep over this chunk (inclusive scan, reverse) ----
    for (int tt = CH - 1; tt >= 0; --tt) {
        int idx = base + tt * ND;
        bool m = read_mask(mraw, idx, isb);
        if (m) { nx = v[idx]; ntm = t[idx]; nv = true; }
        s_next[tt][d] = nv ? make_float2(nx, ntm) : make_float2(0.f, tmax);
    }

    // ---- forward seed: last observation in any earlier chunk ----
    float lx = 0.f, lt = t0; bool lv = false;
    for (int j = c - 1; j >= 0; --j) {
        int s = (b * NC + j) * ND + d;
        if (g_fv[s]) { lx = g_fx[s]; lt = g_ft[s]; lv = true; break; }
    }

    // No __syncthreads needed: each thread only touches its own smem column.

    // ---- forward sweep: inclusive forward fill + interpolation ----
    for (int tt = 0; tt < CH; ++tt) {
        int idx = base + tt * ND;
        bool m = read_mask(mraw, idx, isb);
        float vv = v[idx];
        float tv = t[idx];
        if (m) { lx = vv; lt = tv; lv = true; }

        float xl = lv ? lx : 0.f;
        float tl = lv ? lt : t0;
        float2 nn = s_next[tt][d];          // (x_next, t_next)

        float o;
        if (m) {
            o = vv;
        } else {
            float denom = nn.y - tl;
            if (denom != 0.f) {
                float r = (xl * (nn.y - tv) + nn.x * (tv - tl)) / denom;
                o = isfinite(r) ? r : 0.f;
            } else {
                o = 0.f;
            }
        }
        out[idx] = o;
    }
}

// ---------------------------------------------------------------------------
extern "C" void kernel_launch(void* const* d_in, const int* in_sizes, int n_in,
                              void* d_out, int out_size) {
    const float* values = (const float*)d_in[0];
    const float* times  = (const float*)d_in[1];
    const void*  mask   = d_in[2];

    (void)n_in; (void)in_sizes; (void)out_size;

    // Mask dtype detection (deterministic; same result every replay)
    k_init_flag<<<1, 1>>>();
    const int nwords = 262144;              // 1MB, safe under bool (8MB) layout
    k_detect<<<nwords / 256, 256>>>((const unsigned int*)mask, nwords);

    // Pass 1: chunk summaries
    k_sum<<<NB * NC, ND>>>(values, times, mask);

    // Pass 2: interpolation
    k_interp<<<NB * NC, ND>>>(values, times, mask, (float*)d_out);
}

// round 2
// speedup vs baseline: 1.8766x; 1.8766x over previous
#include <cuda_runtime.h>
#include <cstdint>
#include <math.h>

// Problem shape (fixed by the reference)
#define NB 32
#define NT 2048
#define ND 128
#define CH 16          // timesteps per chunk (bits in one lane-mask word)
#define NC 128         // number of time chunks (NT / CH)

// ---------------------------------------------------------------------------
// Scratch (__device__ globals; no allocations allowed)
// ---------------------------------------------------------------------------
__device__ int g_is_bool;                         // 1 if mask is 1-byte bools
__device__ unsigned int g_mbits[NB * NC * ND];    // per-(b,c,d) observation bits, 2MB

__global__ void k_init_flag() { g_is_bool = 0; }

// Detect mask storage: int32 0/1 mask -> every 32-bit word is 0 or 1.
// Packed 1-byte bools -> words with multiple set bytes appear w.p. ~1 over
// 256K random words. Scans 1MB (safe for both layouts).
__global__ void k_detect(const unsigned int* __restrict__ w, int nwords) {
    int i = blockIdx.x * blockDim.x + threadIdx.x;
    if (i < nwords && w[i] > 1u) g_is_bool = 1;
}

// ---------------------------------------------------------------------------
// Pass 1: stream the mask once, pack per-lane chunk bitmasks.
// Block = (b, chunk c); thread = lane d. Fully coalesced.
// ---------------------------------------------------------------------------
__global__ void __launch_bounds__(ND) k_mask(const void* __restrict__ mraw) {
    const bool isb = (g_is_bool != 0);
    const int blk = blockIdx.x;            // 0 .. NB*NC-1
    const int b = blk / NC;
    const int c = blk % NC;
    const int d = threadIdx.x;

    const int base = (b * NT + c * CH) * ND + d;
    unsigned int bits = 0;

    if (isb) {
        const unsigned char* m = (const unsigned char*)mraw;
#pragma unroll
        for (int tt = 0; tt < CH; ++tt)
            bits |= (m[base + tt * ND] != 0 ? 1u : 0u) << tt;
    } else {
        const int* m = (const int*)mraw;
#pragma unroll
        for (int tt = 0; tt < CH; ++tt)
            bits |= (m[base + tt * ND] != 0 ? 1u : 0u) << tt;
    }
    g_mbits[blk * ND + d] = bits;
}

// ---------------------------------------------------------------------------
// Pass 2: interpolation. Seeds come from g_mbits (L2) + tiny gathers.
// Backward sweep fills (x_next, t_next) into smem and caches t; forward
// sweep computes the exact reference formula with zero global loads.
// ---------------------------------------------------------------------------
__global__ void __launch_bounds__(ND) k_interp(const float* __restrict__ v,
                                               const float* __restrict__ t,
                                               float* __restrict__ out) {
    __shared__ float2 s_nn[CH][ND];   // (x_next, t_next)  16KB
    __shared__ float  s_t [CH][ND];   // cached times       8KB

    const int blk = blockIdx.x;
    const int b = blk / NC;
    const int c = blk % NC;
    const int d = threadIdx.x;

    const unsigned int mb = g_mbits[blk * ND + d];
    const int rowbase = b * NT * ND + d;
    const int base = rowbase + (c * CH) * ND;

    // ---- backward seed: first observation in any later chunk ----
    float nx = 0.f, nt;
    bool nv = false;
    for (int j = c + 1; j < NC; ++j) {
        unsigned int mj = g_mbits[(b * NC + j) * ND + d];
        if (mj) {
            int ti = j * CH + (__ffs(mj) - 1);
            int gi = rowbase + ti * ND;
            nx = v[gi]; nt = t[gi]; nv = true;
            break;
        }
    }
    if (!nv) nt = t[rowbase + (NT - 1) * ND];    // tmax (times are cumsum)

    // ---- backward inclusive sweep over this chunk ----
#pragma unroll
    for (int tt = CH - 1; tt >= 0; --tt) {
        int idx = base + tt * ND;
        float tv = t[idx];
        float vv = v[idx];
        s_t[tt][d] = tv;
        if ((mb >> tt) & 1u) { nx = vv; nt = tv; }
        s_nn[tt][d] = make_float2(nx, nt);
    }

    // ---- forward seed: last observation in any earlier chunk ----
    float lx = 0.f, lt;
    bool lv = false;
    for (int j = c - 1; j >= 0; --j) {
        unsigned int mj = g_mbits[(b * NC + j) * ND + d];
        if (mj) {
            int ti = j * CH + (31 - __clz(mj));
            int gi = rowbase + ti * ND;
            lx = v[gi]; lt = t[gi]; lv = true;
            break;
        }
    }
    if (!lv) lt = t[rowbase];                    // t0 = times[b, 0, d]

    // No __syncthreads needed: each thread touches only its own smem column.

    // ---- forward sweep: inclusive forward fill + interpolation ----
#pragma unroll
    for (int tt = 0; tt < CH; ++tt) {
        float2 nn = s_nn[tt][d];
        float o;
        if ((mb >> tt) & 1u) {
            lx = nn.x; lt = nn.y;                // observed: nn == (v, t) here
            o = nn.x;
        } else {
            float tv = s_t[tt][d];
            float denom = nn.y - lt;
            float num = lx * (nn.y - tv) + nn.x * (tv - lt);
            float r = __fdividef(num, denom);
            o = (denom != 0.f && isfinite(r)) ? r : 0.f;
        }
        out[base + tt * ND] = o;
    }
}

// ---------------------------------------------------------------------------
extern "C" void kernel_launch(void* const* d_in, const int* in_sizes, int n_in,
                              void* d_out, int out_size) {
    const float* values = (const float*)d_in[0];
    const float* times  = (const float*)d_in[1];
    const void*  mask   = d_in[2];

    (void)n_in; (void)in_sizes; (void)out_size;

    // Mask dtype detection (deterministic; same result every replay)
    k_init_flag<<<1, 1>>>();
    const int nwords = 262144;               // 1MB, safe for bool (8MB) layout
    k_detect<<<nwords / 256, 256>>>((const unsigned int*)mask, nwords);

    // Pass 1: pack per-lane chunk bitmasks (streams mask exactly once)
    k_mask<<<NB * NC, ND>>>(mask);

    // Pass 2: interpolation (streams v, t once; writes out once)
    k_interp<<<NB * NC, ND>>>(values, times, (float*)d_out);
}

// round 3
// speedup vs baseline: 1.9940x; 1.0626x over previous
#include <cuda_runtime.h>
#include <cstdint>
#include <math.h>

// Problem shape (fixed by the reference)
#define NB 32
#define NT 2048
#define ND 128
#define CH 8           // timesteps per chunk (bits per lane-mask word)
#define NC 256         // NT / CH

// ---------------------------------------------------------------------------
// Scratch (__device__ globals; no allocations allowed)
// ---------------------------------------------------------------------------
__device__ int g_is_bool;                         // 1 if mask is 1-byte bools
__device__ unsigned int g_mbits[NB * NC * ND];    // per-(b,c,d) observation bits, 4MB

__global__ void k_init_flag() { g_is_bool = 0; }

// Detect mask storage: int32 0/1 mask -> every 32-bit word is 0 or 1.
// Packed 1-byte bools -> words with high bytes set appear w.p. ~1 over 64K
// random words. Scans 256KB (safe for both layouts).
__global__ void k_detect(const unsigned int* __restrict__ w, int nwords) {
    int i = blockIdx.x * blockDim.x + threadIdx.x;
    if (i < nwords && w[i] > 1u) g_is_bool = 1;
}

// ---------------------------------------------------------------------------
// Pass 1: stream the mask once (vectorized), pack per-lane chunk bitmasks.
// Thread = (b, chunk c, 4-lane group). All loads/stores 128-bit or 32-bit word.
// ---------------------------------------------------------------------------
__global__ void __launch_bounds__(128) k_mask(const void* __restrict__ mraw) {
    const int gid = blockIdx.x * 128 + threadIdx.x;
    const int dg = gid & 31;                 // ND/4 = 32 lane groups
    const int c  = (gid >> 5) & (NC - 1);
    const int b  = gid >> 13;                // 5 + log2(NC)
    const int d4 = dg * 4;

    // word/int4 index of (b, c*CH + tt, d4)
    const int base = (b * NT + c * CH) * (ND >> 2) + dg;
    uint4 bits = make_uint4(0u, 0u, 0u, 0u);

    if (g_is_bool != 0) {
        const unsigned int* m = (const unsigned int*)mraw;   // 4 bool bytes / word
#pragma unroll
        for (int tt = 0; tt < CH; ++tt) {
            unsigned int w = m[base + tt * (ND >> 2)];
            bits.x |= ((w         & 0xffu) ? 1u : 0u) << tt;
            bits.y |= (((w >> 8)  & 0xffu) ? 1u : 0u) << tt;
            bits.z |= (((w >> 16) & 0xffu) ? 1u : 0u) << tt;
            bits.w |= (((w >> 24)        ) ? 1u : 0u) << tt;
        }
    } else {
        const int4* m = (const int4*)mraw;
#pragma unroll
        for (int tt = 0; tt < CH; ++tt) {
            int4 w = m[base + tt * (ND >> 2)];
            bits.x |= (w.x ? 1u : 0u) << tt;
            bits.y |= (w.y ? 1u : 0u) << tt;
            bits.z |= (w.z ? 1u : 0u) << tt;
            bits.w |= (w.w ? 1u : 0u) << tt;
        }
    }
    *(uint4*)&g_mbits[(b * NC + c) * ND + d4] = bits;
}

// ---------------------------------------------------------------------------
// Pass 2: interpolation. Thread = (b, chunk c, 2-lane group), all state in
// registers (no smem). float2 loads/stores; seeds from g_mbits (L2).
// ---------------------------------------------------------------------------
__global__ void __launch_bounds__(128) k_interp(const float* __restrict__ v,
                                                const float* __restrict__ t,
                                                float* __restrict__ out) {
    const int gid = blockIdx.x * 128 + threadIdx.x;
    const int dg = gid & 63;                 // ND/2 = 64 lane groups
    const int c  = (gid >> 6) & (NC - 1);
    const int b  = gid >> 14;                // 6 + log2(NC)
    const int d2 = dg * 2;

    const unsigned int* mrow = &g_mbits[b * NC * ND + d2];
    const uint2 mb = *(const uint2*)&mrow[c * ND];

    const int rb = b * NT * ND + d2;         // lane0 scalar row base; lane1 = rb+1
    const float2* v2 = (const float2*)v;
    const float2* t2 = (const float2*)t;
    float2* o2 = (float2*)out;
    const int base2 = (b * NT + c * CH) * (ND / 2) + dg;

    // ---- backward seeds: first observation in any later chunk ----
    float nx0 = 0.f, nx1 = 0.f, nt0, nt1;
    bool nv0 = false, nv1 = false;
    for (int j = c + 1; j < NC; ++j) {
        uint2 mj = *(const uint2*)&mrow[j * ND];
        if (!nv0 && mj.x) { int ti = j * CH + __ffs(mj.x) - 1; int gi = rb + ti * ND;
                            nx0 = v[gi]; nt0 = t[gi]; nv0 = true; }
        if (!nv1 && mj.y) { int ti = j * CH + __ffs(mj.y) - 1; int gi = rb + 1 + ti * ND;
                            nx1 = v[gi]; nt1 = t[gi]; nv1 = true; }
        if (nv0 && nv1) break;
    }
    if (!nv0) nt0 = t[rb + (NT - 1) * ND];       // tmax (times are cumsum)
    if (!nv1) nt1 = t[rb + 1 + (NT - 1) * ND];

    // ---- backward inclusive sweep, all results in registers ----
    float2 TV[CH], NNX[CH], NNT[CH];
#pragma unroll
    for (int tt = CH - 1; tt >= 0; --tt) {
        float2 vv = v2[base2 + tt * (ND / 2)];
        float2 tv = t2[base2 + tt * (ND / 2)];
        TV[tt] = tv;
        if ((mb.x >> tt) & 1u) { nx0 = vv.x; nt0 = tv.x; }
        if ((mb.y >> tt) & 1u) { nx1 = vv.y; nt1 = tv.y; }
        NNX[tt] = make_float2(nx0, nx1);
        NNT[tt] = make_float2(nt0, nt1);
    }

    // ---- forward seeds: last observation in any earlier chunk ----
    float lx0 = 0.f, lx1 = 0.f, lt0, lt1;
    bool lv0 = false, lv1 = false;
    for (int j = c - 1; j >= 0; --j) {
        uint2 mj = *(const uint2*)&mrow[j * ND];
        if (!lv0 && mj.x) { int ti = j * CH + 31 - __clz(mj.x); int gi = rb + ti * ND;
                            lx0 = v[gi]; lt0 = t[gi]; lv0 = true; }
        if (!lv1 && mj.y) { int ti = j * CH + 31 - __clz(mj.y); int gi = rb + 1 + ti * ND;
                            lx1 = v[gi]; lt1 = t[gi]; lv1 = true; }
        if (lv0 && lv1) break;
    }
    if (!lv0) lt0 = t[rb];                       // t0 = times[b, 0, d]
    if (!lv1) lt1 = t[rb + 1];

    // ---- forward sweep: inclusive forward fill + interpolation ----
#pragma unroll
    for (int tt = 0; tt < CH; ++tt) {
        float2 o;
        // lane 0
        if ((mb.x >> tt) & 1u) {
            lx0 = NNX[tt].x; lt0 = NNT[tt].x;    // observed: NN == (v, t) here
            o.x = NNX[tt].x;
        } else {
            float den = NNT[tt].x - lt0;
            float num = lx0 * (NNT[tt].x - TV[tt].x) + NNX[tt].x * (TV[tt].x - lt0);
            float r = __fdividef(num, den);
            o.x = (den != 0.f && isfinite(r)) ? r : 0.f;
        }
        // lane 1
        if ((mb.y >> tt) & 1u) {
            lx1 = NNX[tt].y; lt1 = NNT[tt].y;
            o.y = NNX[tt].y;
        } else {
            float den = NNT[tt].y - lt1;
            float num = lx1 * (NNT[tt].y - TV[tt].y) + NNX[tt].y * (TV[tt].y - lt1);
            float r = __fdividef(num, den);
            o.y = (den != 0.f && isfinite(r)) ? r : 0.f;
        }
        o2[base2 + tt * (ND / 2)] = o;
    }
}

// ---------------------------------------------------------------------------
extern "C" void kernel_launch(void* const* d_in, const int* in_sizes, int n_in,
                              void* d_out, int out_size) {
    const float* values = (const float*)d_in[0];
    const float* times  = (const float*)d_in[1];
    const void*  mask   = d_in[2];

    (void)n_in; (void)in_sizes; (void)out_size;

    // Mask dtype detection (deterministic; same result every replay)
    k_init_flag<<<1, 1>>>();
    const int nwords = 65536;                // 256KB scan, safe for both layouts
    k_detect<<<nwords / 256, 256>>>((const unsigned int*)mask, nwords);

    // Pass 1: pack per-lane chunk bitmasks (streams mask exactly once)
    k_mask<<<(NB * NC * (ND / 4)) / 128, 128>>>(mask);

    // Pass 2: interpolation (streams v, t once; writes out once)
    k_interp<<<(NB * NC * (ND / 2)) / 128, 128>>>(values, times, (float*)d_out);
}